// round 2
// baseline (speedup 1.0000x reference)
#include <cuda_runtime.h>
#include <cuda_bf16.h>
#include <cstddef>

// Problem constants
#define CB 2
#define CT 1024
#define CC 2048
#define CH 16
#define CD 128
#define CP 1024
#define CL 2048   // P + T

// Scratch (allocation-free: device globals)
__device__ float g_q[(size_t)CB * CT * CC];    // scaled Q, [B,T,C] (C = h*D+d)
__device__ float g_att[(size_t)CB * CT * CC];  // attention output pre-projection

// ---------------------------------------------------------------------------
// Copy past KV [B,H,P,D] into cache [B,H,L,D] (first P rows of each bh slab)
// ---------------------------------------------------------------------------
__global__ __launch_bounds__(256) void copy_past_kernel(
    const float* __restrict__ src, float* __restrict__ dst)
{
    const int PD4 = CP * CD / 4;
    const int LD4 = CL * CD / 4;
    int i = blockIdx.x * blockDim.x + threadIdx.x;  // float4 index
    int total = CB * CH * PD4;
    if (i < total) {
        int bh = i / PD4;
        int r = i - bh * PD4;
        reinterpret_cast<float4*>(dst)[(size_t)bh * LD4 + r] =
            reinterpret_cast<const float4*>(src)[i];
    }
}

// ---------------------------------------------------------------------------
// NT GEMM: Y[m,n] = sum_k A[m,k] * Bm[n,k]   (A: [2048,2048], Bm: [2048,2048])
// mode 0: Y[m*C + n] = acc                      (plain scratch)
// mode 1: Y[m*C + n] = acc + bias[n]            (final out projection)
// mode 2: KV-cache scatter: m=b*T+t, n=h*D+d -> Y[((b*H+h)*L + P + t)*D + d]
// Tile 128x128x16, 256 threads, 8x8 per-thread register block.
// ---------------------------------------------------------------------------
__global__ __launch_bounds__(256) void gemm_nt_kernel(
    const float* __restrict__ A, const float* __restrict__ Bm,
    const float* __restrict__ bias, float* __restrict__ Y, int mode)
{
    __shared__ float As[16][132];
    __shared__ float Bs[16][132];
    const int K = CC;
    const int tid = threadIdx.x;
    const int m0 = blockIdx.y * 128;
    const int n0 = blockIdx.x * 128;
    const int tx = tid & 15;
    const int ty = tid >> 4;

    float acc[8][8];
#pragma unroll
    for (int i = 0; i < 8; i++)
#pragma unroll
        for (int j = 0; j < 8; j++) acc[i][j] = 0.0f;

    for (int k0 = 0; k0 < K; k0 += 16) {
#pragma unroll
        for (int p = 0; p < 2; p++) {
            int idx = tid + p * 256;   // float4 index within 128x16 tile
            int row = idx >> 2;        // 0..127
            int kq  = (idx & 3) << 2;  // 0,4,8,12
            float4 a = *reinterpret_cast<const float4*>(A + (size_t)(m0 + row) * K + k0 + kq);
            As[kq + 0][row] = a.x; As[kq + 1][row] = a.y;
            As[kq + 2][row] = a.z; As[kq + 3][row] = a.w;
            float4 b = *reinterpret_cast<const float4*>(Bm + (size_t)(n0 + row) * K + k0 + kq);
            Bs[kq + 0][row] = b.x; Bs[kq + 1][row] = b.y;
            Bs[kq + 2][row] = b.z; Bs[kq + 3][row] = b.w;
        }
        __syncthreads();
#pragma unroll
        for (int kk = 0; kk < 16; kk++) {
            float a[8], b[8];
            *reinterpret_cast<float4*>(a)     = *reinterpret_cast<const float4*>(&As[kk][ty * 8]);
            *reinterpret_cast<float4*>(a + 4) = *reinterpret_cast<const float4*>(&As[kk][ty * 8 + 4]);
            *reinterpret_cast<float4*>(b)     = *reinterpret_cast<const float4*>(&Bs[kk][tx * 8]);
            *reinterpret_cast<float4*>(b + 4) = *reinterpret_cast<const float4*>(&Bs[kk][tx * 8 + 4]);
#pragma unroll
            for (int i = 0; i < 8; i++)
#pragma unroll
                for (int j = 0; j < 8; j++) acc[i][j] += a[i] * b[j];
        }
        __syncthreads();
    }

    if (mode == 2) {
        // One 128-wide column tile == exactly one head (D == 128).
        int b = m0 / CT;
        int h = n0 / CD;
        int tbase = m0 - b * CT;
        float* base = Y + ((size_t)(b * CH + h) * CL + CP) * CD;
#pragma unroll
        for (int i = 0; i < 8; i++) {
            int r = ty * 8 + i;
            float* dst = base + (size_t)(tbase + r) * CD + tx * 8;
            *reinterpret_cast<float4*>(dst) =
                make_float4(acc[i][0], acc[i][1], acc[i][2], acc[i][3]);
            *reinterpret_cast<float4*>(dst + 4) =
                make_float4(acc[i][4], acc[i][5], acc[i][6], acc[i][7]);
        }
    } else {
        float bv[8];
#pragma unroll
        for (int j = 0; j < 8; j++)
            bv[j] = (mode == 1) ? bias[n0 + tx * 8 + j] : 0.0f;
#pragma unroll
        for (int i = 0; i < 8; i++) {
            int r = ty * 8 + i;
            float* dst = Y + (size_t)(m0 + r) * CC + n0 + tx * 8;
            *reinterpret_cast<float4*>(dst) =
                make_float4(acc[i][0] + bv[0], acc[i][1] + bv[1],
                            acc[i][2] + bv[2], acc[i][3] + bv[3]);
            *reinterpret_cast<float4*>(dst + 4) =
                make_float4(acc[i][4] + bv[4], acc[i][5] + bv[5],
                            acc[i][6] + bv[6], acc[i][7] + bv[7]);
        }
    }
}

// ---------------------------------------------------------------------------
// Flash attention (fp32), causal over the full cache.
// grid: (T/32 q-tiles, B*H). block 256 = 8 warps; each warp owns 4 queries.
// Key tiles of 64. smem: Qs[32][128], Ks[64][128] (XOR-swizzled), Vs[64][128],
// Ps[32][64]  => 90112 bytes dynamic.
// ---------------------------------------------------------------------------
__global__ __launch_bounds__(256) void attn_kernel(
    const float* __restrict__ Qg,   // g_q [B,T,C]
    const float* __restrict__ Kc,   // [B,H,L,D]
    const float* __restrict__ Vc,   // [B,H,L,D]
    float* __restrict__ Og)         // g_att [B,T,C]
{
    extern __shared__ float sm[];
    float* Qs = sm;                  //  32*128
    float* Ks = Qs + 32 * 128;       //  64*128 (swizzled)
    float* Vs = Ks + 64 * 128;       //  64*128
    float* Ps = Vs + 64 * 128;       //  32*64

    const int bh = blockIdx.y;
    const int b = bh >> 4;
    const int h = bh & 15;
    const int q0 = blockIdx.x * 32;  // query tile start (t index)
    const int tid = threadIdx.x;
    const int w = tid >> 5;
    const int lane = tid & 31;

    // Load + scale Q tile
    const float scale = 0.08838834764831845f;  // 1/sqrt(128)
    for (int i = tid; i < 32 * 32; i += 256) { // 32 rows x 32 float4
        int q = i >> 5;
        int dq = (i & 31) << 2;
        float4 v = *reinterpret_cast<const float4*>(
            Qg + ((size_t)(b * CT + q0 + q)) * CC + h * CD + dq);
        v.x *= scale; v.y *= scale; v.z *= scale; v.w *= scale;
        *reinterpret_cast<float4*>(Qs + q * 128 + dq) = v;
    }

    const int myq = w * 4;  // local query base for this warp
    float m_i[4], l_i[4], o[4][4];
#pragma unroll
    for (int qq = 0; qq < 4; qq++) {
        m_i[qq] = -1e30f;
        l_i[qq] = 0.0f;
        o[qq][0] = o[qq][1] = o[qq][2] = o[qq][3] = 0.0f;
    }

    const int kmax = CP + q0 + 31;            // highest key pos any query here sees
    const int ntiles = (kmax + 1 + 63) >> 6;  // never exceeds L/64

    const float* Kbase = Kc + (size_t)bh * CL * CD;
    const float* Vbase = Vc + (size_t)bh * CL * CD;

    const int key0 = lane;
    const int key1 = lane + 32;
    const int dl = lane * 4;

    for (int tI = 0; tI < ntiles; tI++) {
        const int j0 = tI * 64;
        __syncthreads();  // previous-iteration smem readers done
        // Load K (swizzled scalar stores) and V (plain float4)
        for (int i = tid; i < 64 * 32; i += 256) {
            int kk = i >> 5;
            int dq = (i & 31) << 2;
            int sw = kk & 31;
            float4 kv = *reinterpret_cast<const float4*>(Kbase + (size_t)(j0 + kk) * CD + dq);
            Ks[kk * 128 + ((dq + 0) ^ sw)] = kv.x;
            Ks[kk * 128 + ((dq + 1) ^ sw)] = kv.y;
            Ks[kk * 128 + ((dq + 2) ^ sw)] = kv.z;
            Ks[kk * 128 + ((dq + 3) ^ sw)] = kv.w;
            float4 vv = *reinterpret_cast<const float4*>(Vbase + (size_t)(j0 + kk) * CD + dq);
            *reinterpret_cast<float4*>(Vs + kk * 128 + dq) = vv;
        }
        __syncthreads();

        // ---- scores: lane-per-key (2 keys/lane), conflict-free via XOR ----
        float s[4][2];
#pragma unroll
        for (int qq = 0; qq < 4; qq++) { s[qq][0] = 0.0f; s[qq][1] = 0.0f; }
        const float* K0 = Ks + key0 * 128;
        const float* K1 = Ks + key1 * 128;
        const int sw0 = key0 & 31;  // == key1 & 31
#pragma unroll 4
        for (int d = 0; d < 128; d++) {
            float k0v = K0[d ^ sw0];
            float k1v = K1[d ^ sw0];
#pragma unroll
            for (int qq = 0; qq < 4; qq++) {
                float qv = Qs[(myq + qq) * 128 + d];
                s[qq][0] += qv * k0v;
                s[qq][1] += qv * k1v;
            }
        }

        // ---- mask + online softmax update ----
#pragma unroll
        for (int qq = 0; qq < 4; qq++) {
            int qp = CP + q0 + myq + qq;
            float s0 = (j0 + key0 <= qp) ? s[qq][0] : -1e30f;
            float s1 = (j0 + key1 <= qp) ? s[qq][1] : -1e30f;
            float mt = fmaxf(s0, s1);
#pragma unroll
            for (int off = 16; off; off >>= 1)
                mt = fmaxf(mt, __shfl_xor_sync(0xffffffffu, mt, off));
            float mnew = fmaxf(m_i[qq], mt);
            float p0 = __expf(s0 - mnew);
            float p1 = __expf(s1 - mnew);
            float psum = p0 + p1;
#pragma unroll
            for (int off = 16; off; off >>= 1)
                psum += __shfl_xor_sync(0xffffffffu, psum, off);
            float alpha = __expf(m_i[qq] - mnew);
            l_i[qq] = l_i[qq] * alpha + psum;
            m_i[qq] = mnew;
            o[qq][0] *= alpha; o[qq][1] *= alpha;
            o[qq][2] *= alpha; o[qq][3] *= alpha;
            Ps[(myq + qq) * 64 + key0] = p0;
            Ps[(myq + qq) * 64 + key1] = p1;
        }
        __syncwarp();

        // ---- PV: lane-per-4-dims, V rows broadcast-free LDS.128 ----
#pragma unroll
        for (int qq = 0; qq < 4; qq++) {
            const float* Pr = Ps + (myq + qq) * 64;
#pragma unroll 4
            for (int k2 = 0; k2 < 64; k2++) {
                float p = Pr[k2];
                float4 vv = *reinterpret_cast<const float4*>(Vs + k2 * 128 + dl);
                o[qq][0] += p * vv.x;
                o[qq][1] += p * vv.y;
                o[qq][2] += p * vv.z;
                o[qq][3] += p * vv.w;
            }
        }
    }

    // ---- finalize ----
#pragma unroll
    for (int qq = 0; qq < 4; qq++) {
        float inv = 1.0f / l_i[qq];
        float4 r = make_float4(o[qq][0] * inv, o[qq][1] * inv,
                               o[qq][2] * inv, o[qq][3] * inv);
        *reinterpret_cast<float4*>(
            Og + (size_t)(b * CT + q0 + myq + qq) * CC + h * CD + dl) = r;
    }
}

// ---------------------------------------------------------------------------
extern "C" void kernel_launch(void* const* d_in, const int* in_sizes, int n_in,
                              void* d_out, int out_size)
{
    const float* x      = (const float*)d_in[0];
    const float* past_k = (const float*)d_in[1];
    const float* past_v = (const float*)d_in[2];
    const float* Wk     = (const float*)d_in[3];
    const float* Wq     = (const float*)d_in[4];
    const float* Wv     = (const float*)d_in[5];
    const float* Wp     = (const float*)d_in[6];
    const float* bp     = (const float*)d_in[7];

    float* out    = (float*)d_out;
    float* kcache = out + (size_t)CB * CT * CC;          // k region
    float* vcache = kcache + (size_t)CB * CH * CL * CD;  // v region

    float* qptr = nullptr;
    float* attptr = nullptr;
    cudaGetSymbolAddress((void**)&qptr, g_q);
    cudaGetSymbolAddress((void**)&attptr, g_att);

    // 1) copy past KV into cache regions of d_out
    int ncopy4 = CB * CH * CP * CD / 4;
    copy_past_kernel<<<(ncopy4 + 255) / 256, 256>>>(past_k, kcache);
    copy_past_kernel<<<(ncopy4 + 255) / 256, 256>>>(past_v, vcache);

    // 2) projections
    dim3 ggrid(16, 16);
    gemm_nt_kernel<<<ggrid, 256>>>(x, Wq, nullptr, qptr, 0);
    gemm_nt_kernel<<<ggrid, 256>>>(x, Wk, nullptr, kcache, 2);
    gemm_nt_kernel<<<ggrid, 256>>>(x, Wv, nullptr, vcache, 2);

    // 3) attention
    cudaFuncSetAttribute(attn_kernel, cudaFuncAttributeMaxDynamicSharedMemorySize, 90112);
    attn_kernel<<<dim3(32, 32), 256, 90112>>>(qptr, kcache, vcache, attptr);

    // 4) output projection + bias
    gemm_nt_kernel<<<ggrid, 256>>>(attptr, Wp, bp, out, 1);
}